// round 6
// baseline (speedup 1.0000x reference)
#include <cuda_runtime.h>
#include <cuda_fp16.h>
#include <math.h>

#define NNODES 250000
#define NEDGES 4000000
#define DIM 64
#define SCAN_B 1024
#define NSCANB ((NNODES + SCAN_B - 1) / SCAN_B)   // 245

// -------- scratch (device globals; allocation is forbidden) --------
// g_deg is zero-initialized at module load; every kernel_launch call re-zeroes
// it (inside k_spmm layer 3) so the NEXT call sees zeros. Deterministic: every
// call performs identical work.
__device__ int    g_deg[NNODES];
__device__ int    g_rowptr[NNODES + 1];
__device__ int    g_fill[NNODES];
__device__ int    g_col[NEDGES];
__device__ float  g_dis[NNODES];
__device__ int    g_blocksum[NSCANB];
// pre-scaled features s[r] = dis[r]*feat[r], fp16 packed: 8 float4 = 128 B per
// row, 128B-aligned so each gathered row is exactly one L2 line.
__device__ __align__(128) float4 g_sA[(size_t)NNODES * 8];
__device__ __align__(128) float4 g_sB[(size_t)NNODES * 8];

// -------- CSR build --------
__global__ void k_count(const int* __restrict__ edge) {
    int e = blockIdx.x * blockDim.x + threadIdx.x;
    if (e < NEDGES) atomicAdd(&g_deg[__ldcs(&edge[e])], 1);
}

// warp-shuffle block scan (exclusive), block totals to g_blocksum
__global__ void k_scan1() {
    __shared__ int warp_tot[SCAN_B / 32];
    int i = blockIdx.x * SCAN_B + threadIdx.x;
    int lane = threadIdx.x & 31;
    int wid  = threadIdx.x >> 5;
    int v = (i < NNODES) ? g_deg[i] : 0;

    int x = v;                                   // inclusive warp scan
    #pragma unroll
    for (int off = 1; off < 32; off <<= 1) {
        int t = __shfl_up_sync(0xffffffffu, x, off);
        if (lane >= off) x += t;
    }
    if (lane == 31) warp_tot[wid] = x;
    __syncthreads();

    if (wid == 0) {                              // scan the 32 warp totals
        int wt = warp_tot[lane];
        int y = wt;
        #pragma unroll
        for (int off = 1; off < 32; off <<= 1) {
            int t = __shfl_up_sync(0xffffffffu, y, off);
            if (lane >= off) y += t;
        }
        warp_tot[lane] = y - wt;                 // exclusive
        if (lane == 31) g_blocksum[blockIdx.x] = y;
    }
    __syncthreads();

    if (i < NNODES) g_rowptr[i] = x - v + warp_tot[wid];   // block-local exclusive
}

// merged scan2+scan3: each block computes its own blocksum prefix (245 ints),
// finalizes rowptr, fill cursors, and dis.
__global__ void k_scan23() {
    __shared__ int s_off;
    int b = blockIdx.x;
    if (threadIdx.x < 32) {
        int partial = 0;
        for (int i = threadIdx.x; i < b; i += 32) partial += g_blocksum[i];
        #pragma unroll
        for (int off = 16; off; off >>= 1)
            partial += __shfl_xor_sync(0xffffffffu, partial, off);
        if (threadIdx.x == 0) s_off = partial;
    }
    __syncthreads();
    int i = b * SCAN_B + threadIdx.x;
    if (i < NNODES) {
        int v = g_rowptr[i] + s_off;
        g_rowptr[i] = v;
        g_fill[i]   = v;
        g_dis[i]    = rsqrtf((float)(g_deg[i] + 1));   // +1 self loop; > 0
    }
    if (i == 0) g_rowptr[NNODES] = NEDGES;
}

// fused: CSR column fill (edge-parallel) + s0 = dis*emb fp16 pack (node-chunk
// parallel). The two jobs are independent; both depend only on scan23.
__global__ void k_fillscale(const int* __restrict__ edge,
                            const float* __restrict__ emb) {
    int t = blockIdx.x * blockDim.x + threadIdx.x;
    if (t < NEDGES) {
        int r = __ldcs(&edge[t]);
        int c = __ldcs(&edge[NEDGES + t]);
        int slot = atomicAdd(&g_fill[r], 1);
        g_col[slot] = c;
    }
    if (t < NNODES * 8) {
        int r = t >> 3;
        int chunk = t & 7;
        float d = g_dis[r];
        const float4* e4 = (const float4*)emb;   // 16 float4 per row
        float4 a = __ldcs(&e4[(size_t)r * 16 + chunk * 2]);
        float4 b = __ldcs(&e4[(size_t)r * 16 + chunk * 2 + 1]);
        float4 outv;
        __half2* h = (__half2*)&outv;
        h[0] = __floats2half2_rn(d * a.x, d * a.y);
        h[1] = __floats2half2_rn(d * a.z, d * a.w);
        h[2] = __floats2half2_rn(d * b.x, d * b.y);
        h[3] = __floats2half2_rn(d * b.z, d * b.w);
        g_sA[t] = outv;
    }
}

__device__ __forceinline__ void add8(float* acc, float4 v) {
    __half2* h = (__half2*)&v;
    #pragma unroll
    for (int i = 0; i < 4; i++) {
        float2 f = __half22float2(h[i]);
        acc[2 * i]     += f.x;
        acc[2 * i + 1] += f.y;
    }
}

// -------- SpMM: 1 warp/row, 4 edges per LDG.128 --------
// lane group g = lane>>3 owns edge e+g; chunk = lane&7 owns dims [chunk*8,+8)
__global__ void __launch_bounds__(256) k_spmm(
                       const float4* __restrict__ sin,
                       float4* __restrict__ sout,             // nullable
                       float* __restrict__ o1, int s1,
                       float* __restrict__ o2, int s2,        // o2 nullable
                       int zdeg) {
    int t = blockIdx.x * blockDim.x + threadIdx.x;
    if (zdeg && t < NNODES) g_deg[t] = 0;        // deferred zero for next call
    int warp = t >> 5;
    if (warp >= NNODES) return;
    int lane  = threadIdx.x & 31;
    int g     = lane >> 3;
    int chunk = lane & 7;
    int r = warp;

    int beg = g_rowptr[r];
    int end = g_rowptr[r + 1];
    float dr = g_dis[r];

    float acc[8];
    #pragma unroll
    for (int i = 0; i < 8; i++) acc[i] = 0.f;
    if (g == 3) add8(acc, __ldg(&sin[(size_t)r * 8 + chunk]));   // self term

    int e = beg;
    for (; e + 8 <= end; e += 8) {
        int c0 = __ldcs(&g_col[e + g]);
        int c1 = __ldcs(&g_col[e + 4 + g]);
        float4 v0 = __ldg(&sin[(size_t)c0 * 8 + chunk]);
        float4 v1 = __ldg(&sin[(size_t)c1 * 8 + chunk]);
        add8(acc, v0);
        add8(acc, v1);
    }
    for (; e < end; e += 4) {
        int idx = e + g;
        bool valid = idx < end;
        int c = valid ? __ldcs(&g_col[idx]) : r;
        float4 v = __ldg(&sin[(size_t)c * 8 + chunk]);
        if (valid) add8(acc, v);
    }

    #pragma unroll
    for (int i = 0; i < 8; i++) {
        acc[i] += __shfl_xor_sync(0xffffffffu, acc[i], 8);
        acc[i] += __shfl_xor_sync(0xffffffffu, acc[i], 16);
    }

    float outv[8];
    #pragma unroll
    for (int i = 0; i < 8; i++) outv[i] = dr * acc[i];

    if (g == 0) {
        float4* dst = (float4*)(o1 + (size_t)r * s1 + chunk * 8);
        __stcs(dst,     make_float4(outv[0], outv[1], outv[2], outv[3]));
        __stcs(dst + 1, make_float4(outv[4], outv[5], outv[6], outv[7]));
    } else if (g == 1 && o2) {
        float4* dst = (float4*)(o2 + (size_t)r * s2 + chunk * 8);
        __stcs(dst,     make_float4(outv[0], outv[1], outv[2], outv[3]));
        __stcs(dst + 1, make_float4(outv[4], outv[5], outv[6], outv[7]));
    } else if (g == 2 && sout) {
        float dr2 = dr * dr;
        float4 packed;
        __half2* h = (__half2*)&packed;
        h[0] = __floats2half2_rn(dr2 * acc[0], dr2 * acc[1]);
        h[1] = __floats2half2_rn(dr2 * acc[2], dr2 * acc[3]);
        h[2] = __floats2half2_rn(dr2 * acc[4], dr2 * acc[5]);
        h[3] = __floats2half2_rn(dr2 * acc[6], dr2 * acc[7]);
        sout[(size_t)r * 8 + chunk] = packed;    // next layer's gather source
    }
}

extern "C" void kernel_launch(void* const* d_in, const int* in_sizes, int n_in,
                              void* d_out, int out_size) {
    const int*   edge = (const int*)d_in[0];    // [2, NEDGES] int32
    const float* emb  = (const float*)d_in[1];  // [NNODES, 64] f32
    float* out = (float*)d_out;                 // [N*3*64] all_feat + [N*64] final

    float4 *sA, *sB;
    cudaGetSymbolAddress((void**)&sA, g_sA);
    cudaGetSymbolAddress((void**)&sB, g_sB);

    const int T = 256;
    // ---- CSR build (g_deg arrives zeroed from previous call / static init) ----
    k_count<<<(NEDGES + T - 1) / T, T>>>(edge);          // 1
    k_scan1<<<NSCANB, SCAN_B>>>();                       // 2
    k_scan23<<<NSCANB, SCAN_B>>>();                      // 3
    k_fillscale<<<(NEDGES + T - 1) / T, T>>>(edge, emb); // 4

    // ---- 3 propagation layers ----
    // all_feat perm (2,0,1): out[:,0,:]=L3, out[:,1,:]=L1, out[:,2,:]=L2; final=L3
    int spmm_blocks = (NNODES * 32 + T - 1) / T;
    float* out_final = out + (size_t)NNODES * 3 * DIM;

    k_spmm<<<spmm_blocks, T>>>(sA, sB, out + DIM,     3 * DIM, nullptr,  0, 0);     // 5: L1
    k_spmm<<<spmm_blocks, T>>>(sB, sA, out + 2 * DIM, 3 * DIM, nullptr,  0, 0);     // 6: L2
    k_spmm<<<spmm_blocks, T>>>(sA, nullptr, out,      3 * DIM, out_final, DIM, 1);  // 7: L3
}